// round 1
// baseline (speedup 1.0000x reference)
#include <cuda_runtime.h>
#include <cuda_bf16.h>
#include <cstdint>

#define XLD 264   // padded row stride (bf16 elems) for Xs: 528B -> 4-bank skew/row, conflict-free frags
#define WLD 264

// smem layout (bytes):
//   Xs:  128 x 264 bf16 = 67584
//   Ws:  256 x 264 bf16 = 135168
//   floats: tvec 256 | sx 128 | score 128 | b1s 256 | w2s 256 | red 16 | misc 4
static constexpr int SMEM_BYTES =
    128 * XLD * 2 + 256 * WLD * 2 + (256 + 128 + 128 + 256 + 256 + 16 + 4) * 4;

__global__ __launch_bounds__(256, 1)
void nais_kernel(const int* __restrict__ history,
                 const int* __restrict__ target,
                 const int* __restrict__ hregion,
                 const int* __restrict__ tregion,
                 const float* __restrict__ tdist,
                 const float* __restrict__ E_hist,
                 const float* __restrict__ E_tgt,
                 const float* __restrict__ E_reg,
                 const float* __restrict__ E_dist,
                 const float* __restrict__ W1,
                 const float* __restrict__ b1,
                 const float* __restrict__ w2,
                 float* __restrict__ out,
                 int B, int H)
{
    extern __shared__ unsigned char smem_raw[];
    __nv_bfloat16* Xs = (__nv_bfloat16*)smem_raw;            // [128][XLD]
    __nv_bfloat16* Ws = Xs + 128 * XLD;                      // [256][WLD]
    float* tvec   = (float*)(Ws + 256 * WLD);                // [256]
    float* sx     = tvec + 256;                              // [128] fp32 row sums of x
    float* scoreS = sx + 128;                                // [128]
    float* b1s    = scoreS + 128;                            // [256]
    float* w2s    = b1s + 256;                               // [256]
    float* redS   = w2s + 256;                               // [16]
    float* misc   = redS + 16;                               // [0] = sum(E_dist[0])

    const int b    = blockIdx.x;
    const int tid  = threadIdx.x;
    const int warp = tid >> 5;
    const int lane = tid & 31;

    const int tgtI  = target[b];
    const int tregI = tregion[b];

    // ---------------- phase A: target vector, b1/w2, dist-row sum ----------------
    {
        float tv = (tid < 128) ? E_tgt[(size_t)tgtI * 128 + tid]
                               : E_reg[(size_t)tregI * 128 + (tid - 128)];
        tvec[tid] = tv;
        b1s[tid]  = b1[tid];
        w2s[tid]  = w2[tid];
        if (warp == 0) {
            float v = E_dist[lane] + E_dist[lane + 32] + E_dist[lane + 64] + E_dist[lane + 96];
            #pragma unroll
            for (int o = 16; o; o >>= 1) v += __shfl_down_sync(0xffffffffu, v, o);
            if (lane == 0) misc[0] = v;
        }
    }
    __syncthreads();

    // ---------------- phase B: stage W1 (bf16) and X = hist*tgt (bf16 + fp32 sums) ----------------
    for (int i = tid; i < 256 * 64; i += 256) {      // 64 float4 per row
        int row = i >> 6;
        int c4  = (i & 63) << 2;
        float4 v = *(const float4*)(W1 + row * 256 + c4);
        union { __nv_bfloat16 h[4]; uint2 u; } pk;
        pk.h[0] = __float2bfloat16(v.x);
        pk.h[1] = __float2bfloat16(v.y);
        pk.h[2] = __float2bfloat16(v.z);
        pk.h[3] = __float2bfloat16(v.w);
        *(uint2*)(Ws + row * WLD + c4) = pk.u;
    }

    {
        float4 t1 = *(const float4*)(tvec + 4 * lane);        // cols [4l,4l+3]
        float4 t2 = *(const float4*)(tvec + 128 + 4 * lane);  // cols [128+4l..]
        for (int h = warp; h < 128; h += 8) {                 // one warp per row
            union { __nv_bfloat16 q[4]; uint2 u; } p1, p2;
            float s = 0.f;
            if (h < H) {
                int item = history[(size_t)b * H + h];
                int rg   = hregion[(size_t)b * H + h];
                float4 v1 = *(const float4*)(E_hist + (size_t)item * 128 + 4 * lane);
                float4 v2 = *(const float4*)(E_reg  + (size_t)rg   * 128 + 4 * lane);
                float x0 = v1.x * t1.x, x1 = v1.y * t1.y, x2 = v1.z * t1.z, x3 = v1.w * t1.w;
                float y0 = v2.x * t2.x, y1 = v2.y * t2.y, y2 = v2.z * t2.z, y3 = v2.w * t2.w;
                s = (x0 + x1) + (x2 + x3) + (y0 + y1) + (y2 + y3);
                p1.q[0] = __float2bfloat16(x0); p1.q[1] = __float2bfloat16(x1);
                p1.q[2] = __float2bfloat16(x2); p1.q[3] = __float2bfloat16(x3);
                p2.q[0] = __float2bfloat16(y0); p2.q[1] = __float2bfloat16(y1);
                p2.q[2] = __float2bfloat16(y2); p2.q[3] = __float2bfloat16(y3);
            } else {
                p1.u = make_uint2(0u, 0u);
                p2.u = make_uint2(0u, 0u);
            }
            *(uint2*)(Xs + h * XLD + 4 * lane)       = p1.u;
            *(uint2*)(Xs + h * XLD + 128 + 4 * lane) = p2.u;
            #pragma unroll
            for (int o = 16; o; o >>= 1) s += __shfl_down_sync(0xffffffffu, s, o);
            if (lane == 0) sx[h] = s;
        }
    }
    __syncthreads();

    // ---------------- GEMM: C[h,k] = sum_j Xs[h,j]*Ws[k,j], fused relu/b1/w2 epilogue ----------------
    // warp w owns rows [16w, 16w+16); loops N in 4 chunks of 64; K = 256 in 16 mma steps.
    {
        const int g  = lane >> 2;      // groupID
        const int tg = lane & 3;       // thread-in-group
        const int mrow = warp << 4;
        const __nv_bfloat16* Xr0 = Xs + (mrow + g) * XLD + tg * 2;
        const __nv_bfloat16* Xr1 = Xs + (mrow + g + 8) * XLD + tg * 2;
        float sp0 = 0.f, sp1 = 0.f;    // partial scores for rows (mrow+g), (mrow+g+8)

        for (int nc = 0; nc < 4; ++nc) {
            const int nbase = nc << 6;
            float c[8][4];
            #pragma unroll
            for (int nt = 0; nt < 8; ++nt) { c[nt][0] = c[nt][1] = c[nt][2] = c[nt][3] = 0.f; }

            #pragma unroll 4
            for (int kk = 0; kk < 16; ++kk) {
                const int kb = kk << 4;
                uint32_t a0 = *(const uint32_t*)(Xr0 + kb);
                uint32_t a1 = *(const uint32_t*)(Xr1 + kb);
                uint32_t a2 = *(const uint32_t*)(Xr0 + kb + 8);
                uint32_t a3 = *(const uint32_t*)(Xr1 + kb + 8);
                #pragma unroll
                for (int nt = 0; nt < 8; ++nt) {
                    const __nv_bfloat16* Wr = Ws + (nbase + (nt << 3) + g) * WLD + kb + tg * 2;
                    uint32_t bb0 = *(const uint32_t*)(Wr);
                    uint32_t bb1 = *(const uint32_t*)(Wr + 8);
                    asm volatile(
                        "mma.sync.aligned.m16n8k16.row.col.f32.bf16.bf16.f32 "
                        "{%0,%1,%2,%3}, {%4,%5,%6,%7}, {%8,%9}, {%0,%1,%2,%3};\n"
                        : "+f"(c[nt][0]), "+f"(c[nt][1]), "+f"(c[nt][2]), "+f"(c[nt][3])
                        : "r"(a0), "r"(a1), "r"(a2), "r"(a3), "r"(bb0), "r"(bb1));
                }
            }
            // epilogue for this fully-accumulated N chunk
            #pragma unroll
            for (int nt = 0; nt < 8; ++nt) {
                int k0 = nbase + (nt << 3) + (tg << 1);
                float w0 = w2s[k0], w1v = w2s[k0 + 1];
                float q0 = b1s[k0], q1 = b1s[k0 + 1];
                sp0 += fmaxf(c[nt][0] + q0, 0.f) * w0 + fmaxf(c[nt][1] + q1, 0.f) * w1v;
                sp1 += fmaxf(c[nt][2] + q0, 0.f) * w0 + fmaxf(c[nt][3] + q1, 0.f) * w1v;
            }
        }
        // reduce across the 4 lanes of each group (they share rows)
        sp0 += __shfl_xor_sync(0xffffffffu, sp0, 1);
        sp0 += __shfl_xor_sync(0xffffffffu, sp0, 2);
        sp1 += __shfl_xor_sync(0xffffffffu, sp1, 1);
        sp1 += __shfl_xor_sync(0xffffffffu, sp1, 2);
        if (tg == 0) {
            scoreS[mrow + g]     = sp0;
            scoreS[mrow + g + 8] = sp1;
        }
    }
    __syncthreads();

    // ---------------- final: masked exp, sqrt-normalized attention, pred, sigmoid ----------------
    float eS = 0.f, eP = 0.f;
    if (tid < H && tid < 128) {
        float sc = scoreS[tid] + tdist[b] * misc[0];
        float e  = expf(sc);
        if (history[(size_t)b * H + tid] == tgtI) e = 0.f;
        eS = e;
        eP = e * sx[tid];
    }
    #pragma unroll
    for (int o = 16; o; o >>= 1) {
        eS += __shfl_down_sync(0xffffffffu, eS, o);
        eP += __shfl_down_sync(0xffffffffu, eP, o);
    }
    if (lane == 0) { redS[warp] = eS; redS[8 + warp] = eP; }
    __syncthreads();
    if (tid == 0) {
        float S = 0.f, P = 0.f;
        #pragma unroll
        for (int i = 0; i < 8; ++i) { S += redS[i]; P += redS[8 + i]; }
        float pred = P / sqrtf(S);   // attn = exp_A / sum^0.5 (BETA=0.5)
        out[b] = 1.f / (1.f + expf(-pred));
    }
}

extern "C" void kernel_launch(void* const* d_in, const int* in_sizes, int n_in,
                              void* d_out, int out_size)
{
    const int*   history = (const int*)d_in[0];
    const int*   target  = (const int*)d_in[1];
    const int*   hregion = (const int*)d_in[2];
    const int*   tregion = (const int*)d_in[3];
    const float* tdist   = (const float*)d_in[4];
    const float* E_hist  = (const float*)d_in[5];
    const float* E_tgt   = (const float*)d_in[6];
    const float* E_reg   = (const float*)d_in[7];
    const float* E_dist  = (const float*)d_in[8];
    const float* W1      = (const float*)d_in[9];
    const float* b1      = (const float*)d_in[10];
    const float* w2      = (const float*)d_in[11];
    float* out = (float*)d_out;

    const int B = in_sizes[1];                 // target: [B]
    const int H = in_sizes[0] / B;             // history: [B,H]

    cudaFuncSetAttribute(nais_kernel, cudaFuncAttributeMaxDynamicSharedMemorySize, SMEM_BYTES);
    nais_kernel<<<B, 256, SMEM_BYTES>>>(history, target, hregion, tregion, tdist,
                                        E_hist, E_tgt, E_reg, E_dist,
                                        W1, b1, w2, out, B, H);
}

// round 3
// speedup vs baseline: 1.8913x; 1.8913x over previous
#include <cuda_runtime.h>
#include <cuda_bf16.h>
#include <cstdint>

#define WLD 264   // padded row stride (bf16): 528B -> 4-bank skew per row, conflict-free
#define XLD 264

// W1 pre-converted to bf16 in padded row-major [256][WLD]
__device__ __align__(16) __nv_bfloat16 g_W1b[256 * WLD];

// smem (bytes):
//   Ws: 256*264*2 = 135168
//   Xs: 128*264*2 =  67584   (rows >= H hold garbage; their outputs are discarded)
//   floats: b1s 256 | w2s 256 | sx 128 | spp 512 | redS 16 | miscF 4  = 1172 f
static constexpr int SM_W = 0;
static constexpr int SM_X = 256 * WLD * 2;                  // 135168
static constexpr int SM_F = SM_X + 128 * XLD * 2;           // 202752
static constexpr int SMEM_BYTES = SM_F + 1184 * 4;          // 207488

__global__ void convert_w_kernel(const float* __restrict__ W1) {
    int e = blockIdx.x * blockDim.x + threadIdx.x;   // 65536 total
    int n = e >> 8, k = e & 255;
    g_W1b[n * WLD + k] = __float2bfloat16(W1[n * 256 + k]);
}

__global__ __launch_bounds__(512, 1)
void nais_kernel(const int* __restrict__ history,
                 const int* __restrict__ target,
                 const int* __restrict__ hregion,
                 const int* __restrict__ tregion,
                 const float* __restrict__ tdist,
                 const float* __restrict__ E_hist,
                 const float* __restrict__ E_tgt,
                 const float* __restrict__ E_reg,
                 const float* __restrict__ E_dist,
                 const float* __restrict__ b1,
                 const float* __restrict__ w2,
                 float* __restrict__ out,
                 int B, int H, int G)
{
    extern __shared__ unsigned char smem[];
    __nv_bfloat16* Ws = (__nv_bfloat16*)(smem + SM_W);      // [256][WLD]
    __nv_bfloat16* Xs = (__nv_bfloat16*)(smem + SM_X);      // [128][XLD]
    float* fl    = (float*)(smem + SM_F);
    float* b1s   = fl;            // 256
    float* w2s   = fl + 256;      // 256
    float* sx    = fl + 512;      // 128  fp32 row sums of x
    float* spp   = fl + 640;      // 512  per-nw partial scores [4][128]
    float* redS  = fl + 1152;     // 16
    float* miscF = fl + 1168;     // 1 : sum(E_dist[0])

    const int tid  = threadIdx.x;
    const int wid  = tid >> 5;
    const int lane = tid & 31;

    const int bbase = blockIdx.x * G;
    if (bbase >= B) return;
    const int gcnt = min(G, B - bbase);

    // ---------------- one-time staging ----------------
    {
        const uint4* src = (const uint4*)g_W1b;
        uint4* dst = (uint4*)Ws;
        #pragma unroll 4
        for (int i = tid; i < 256 * WLD * 2 / 16; i += 512) dst[i] = src[i];
        if (tid < 256) { b1s[tid] = b1[tid]; w2s[tid] = w2[tid]; }
        if (wid == 0) {
            float v = E_dist[lane] + E_dist[lane + 32] + E_dist[lane + 64] + E_dist[lane + 96];
            #pragma unroll
            for (int o = 16; o; o >>= 1) v += __shfl_down_sync(0xffffffffu, v, o);
            if (lane == 0) miscF[0] = v;
        }
    }
    __syncthreads();
    const float distsum = miscF[0];

    const int mw = wid >> 2;          // 0..3 : rows [32mw, 32mw+32)
    const int nw = wid & 3;           // 0..3 : cols [64nw, 64nw+64)
    const int g  = lane >> 2;
    const int tg = lane & 3;
    const int r0 = mw * 32 + g;

    for (int gi = 0; gi < gcnt; ++gi) {
        const int batch = bbase + gi;
        const int tgtI  = target[batch];

        // ---------------- gather X = hist (*) tgt into SMEM (bf16) + fp32 row sums ----------------
        {
            const int tregI = tregion[batch];
            float4 t1 = *(const float4*)(E_tgt + (size_t)tgtI  * 128 + 4 * lane);
            float4 t2 = *(const float4*)(E_reg + (size_t)tregI * 128 + 4 * lane);
            for (int h = wid; h < H; h += 16) {
                int item = history[(size_t)batch * H + h];
                int rg   = hregion[(size_t)batch * H + h];
                float4 v1 = *(const float4*)(E_hist + (size_t)item * 128 + 4 * lane);
                float4 v2 = *(const float4*)(E_reg  + (size_t)rg   * 128 + 4 * lane);
                float x0 = v1.x * t1.x, x1 = v1.y * t1.y, x2 = v1.z * t1.z, x3 = v1.w * t1.w;
                float y0 = v2.x * t2.x, y1 = v2.y * t2.y, y2 = v2.z * t2.z, y3 = v2.w * t2.w;
                union { __nv_bfloat16 q[4]; uint2 u; } p1, p2;
                p1.q[0] = __float2bfloat16(x0); p1.q[1] = __float2bfloat16(x1);
                p1.q[2] = __float2bfloat16(x2); p1.q[3] = __float2bfloat16(x3);
                p2.q[0] = __float2bfloat16(y0); p2.q[1] = __float2bfloat16(y1);
                p2.q[2] = __float2bfloat16(y2); p2.q[3] = __float2bfloat16(y3);
                *(uint2*)(Xs + h * XLD + 4 * lane)       = p1.u;
                *(uint2*)(Xs + h * XLD + 128 + 4 * lane) = p2.u;
                float s = (x0 + x1) + (x2 + x3) + (y0 + y1) + (y2 + y3);
                #pragma unroll
                for (int o = 16; o; o >>= 1) s += __shfl_down_sync(0xffffffffu, s, o);
                if (lane == 0) sx[h] = s;
            }
        }
        __syncthreads();

        // ---------------- GEMM: warp = m32 x n64, K=256; acc held across K ----------------
        {
            float acc[2][8][4];
            #pragma unroll
            for (int mt = 0; mt < 2; ++mt)
                #pragma unroll
                for (int nt = 0; nt < 8; ++nt)
                    #pragma unroll
                    for (int i = 0; i < 4; ++i) acc[mt][nt][i] = 0.f;

            const __nv_bfloat16* Xr = Xs + r0 * XLD + tg * 2;
            const __nv_bfloat16* Wr0 = Ws + (nw * 64 + g) * WLD + tg * 2;

            #pragma unroll 2
            for (int kk = 0; kk < 16; ++kk) {
                const int kb = kk << 4;
                uint32_t a[2][4];
                #pragma unroll
                for (int mt = 0; mt < 2; ++mt) {
                    const __nv_bfloat16* xr = Xr + mt * 16 * XLD + kb;
                    a[mt][0] = *(const uint32_t*)(xr);
                    a[mt][1] = *(const uint32_t*)(xr + 8 * XLD);
                    a[mt][2] = *(const uint32_t*)(xr + 8);
                    a[mt][3] = *(const uint32_t*)(xr + 8 * XLD + 8);
                }
                #pragma unroll
                for (int nt = 0; nt < 8; ++nt) {
                    const __nv_bfloat16* wr = Wr0 + nt * 8 * WLD + kb;
                    uint32_t b0 = *(const uint32_t*)(wr);
                    uint32_t b1r = *(const uint32_t*)(wr + 8);
                    #pragma unroll
                    for (int mt = 0; mt < 2; ++mt) {
                        asm volatile(
                            "mma.sync.aligned.m16n8k16.row.col.f32.bf16.bf16.f32 "
                            "{%0,%1,%2,%3}, {%4,%5,%6,%7}, {%8,%9}, {%0,%1,%2,%3};\n"
                            : "+f"(acc[mt][nt][0]), "+f"(acc[mt][nt][1]),
                              "+f"(acc[mt][nt][2]), "+f"(acc[mt][nt][3])
                            : "r"(a[mt][0]), "r"(a[mt][1]), "r"(a[mt][2]), "r"(a[mt][3]),
                              "r"(b0), "r"(b1r));
                    }
                }
            }

            // epilogue: relu(+b1) dot w2 over this warp's n64 chunk
            float s0 = 0.f, s1 = 0.f, s2 = 0.f, s3 = 0.f;
            #pragma unroll
            for (int nt = 0; nt < 8; ++nt) {
                int k0 = nw * 64 + nt * 8 + tg * 2;
                float w0 = w2s[k0], w1v = w2s[k0 + 1];
                float q0 = b1s[k0], q1 = b1s[k0 + 1];
                s0 += fmaxf(acc[0][nt][0] + q0, 0.f) * w0 + fmaxf(acc[0][nt][1] + q1, 0.f) * w1v;
                s1 += fmaxf(acc[0][nt][2] + q0, 0.f) * w0 + fmaxf(acc[0][nt][3] + q1, 0.f) * w1v;
                s2 += fmaxf(acc[1][nt][0] + q0, 0.f) * w0 + fmaxf(acc[1][nt][1] + q1, 0.f) * w1v;
                s3 += fmaxf(acc[1][nt][2] + q0, 0.f) * w0 + fmaxf(acc[1][nt][3] + q1, 0.f) * w1v;
            }
            s0 += __shfl_xor_sync(0xffffffffu, s0, 1); s0 += __shfl_xor_sync(0xffffffffu, s0, 2);
            s1 += __shfl_xor_sync(0xffffffffu, s1, 1); s1 += __shfl_xor_sync(0xffffffffu, s1, 2);
            s2 += __shfl_xor_sync(0xffffffffu, s2, 1); s2 += __shfl_xor_sync(0xffffffffu, s2, 2);
            s3 += __shfl_xor_sync(0xffffffffu, s3, 1); s3 += __shfl_xor_sync(0xffffffffu, s3, 2);
            if (tg == 0) {
                float* sp = spp + nw * 128;
                sp[r0]      = s0;
                sp[r0 + 8]  = s1;
                sp[r0 + 16] = s2;
                sp[r0 + 24] = s3;
            }
        }
        __syncthreads();

        // ---------------- masked exp, BETA=0.5 normalize, pred, sigmoid ----------------
        {
            float eS = 0.f, eP = 0.f;
            if (tid < 128 && tid < H) {
                float sc = spp[tid] + spp[128 + tid] + spp[256 + tid] + spp[384 + tid]
                         + tdist[batch] * distsum;
                float e = expf(sc);
                if (history[(size_t)batch * H + tid] == tgtI) e = 0.f;
                eS = e; eP = e * sx[tid];
            }
            #pragma unroll
            for (int o = 16; o; o >>= 1) {
                eS += __shfl_down_sync(0xffffffffu, eS, o);
                eP += __shfl_down_sync(0xffffffffu, eP, o);
            }
            if (wid < 4 && lane == 0) { redS[wid] = eS; redS[8 + wid] = eP; }
        }
        __syncthreads();
        if (tid == 0) {
            float S = redS[0] + redS[1] + redS[2] + redS[3];
            float P = redS[8] + redS[9] + redS[10] + redS[11];
            float pred = P / sqrtf(S);     // attn = exp_A / sum^BETA, BETA=0.5
            out[batch] = 1.f / (1.f + expf(-pred));
        }
        __syncthreads();   // protect sx / Xs / spp before next batch overwrites
    }
}

extern "C" void kernel_launch(void* const* d_in, const int* in_sizes, int n_in,
                              void* d_out, int out_size)
{
    const int*   history = (const int*)d_in[0];
    const int*   target  = (const int*)d_in[1];
    const int*   hregion = (const int*)d_in[2];
    const int*   tregion = (const int*)d_in[3];
    const float* tdist   = (const float*)d_in[4];
    const float* E_hist  = (const float*)d_in[5];
    const float* E_tgt   = (const float*)d_in[6];
    const float* E_reg   = (const float*)d_in[7];
    const float* E_dist  = (const float*)d_in[8];
    const float* W1      = (const float*)d_in[9];
    const float* b1      = (const float*)d_in[10];
    const float* w2      = (const float*)d_in[11];
    float* out = (float*)d_out;

    const int B = in_sizes[1];                 // target: [B]
    const int H = in_sizes[0] / B;             // history: [B,H]

    convert_w_kernel<<<64, 1024>>>(W1);

    const int G = (B + 147) / 148;             // batches per persistent block (1 wave)
    const int grid = (B + G - 1) / G;
    cudaFuncSetAttribute(nais_kernel, cudaFuncAttributeMaxDynamicSharedMemorySize, SMEM_BYTES);
    nais_kernel<<<grid, 512, SMEM_BYTES>>>(history, target, hregion, tregion, tdist,
                                           E_hist, E_tgt, E_reg, E_dist,
                                           b1, w2, out, B, H, G);
}